// round 2
// baseline (speedup 1.0000x reference)
#include <cuda_runtime.h>
#include <cstdint>
#include <cstddef>

#define TL 512
#define NB 2048
#define FULL 0xffffffffu

// scratch: h_seq and z_seq, each T*B*16 floats = 64 MiB
__device__ float g_hseq[(size_t)TL * NB * 16];
__device__ float g_zseq[(size_t)TL * NB * 16];

__device__ __forceinline__ float sigf(float x){
  return __fdividef(1.f, 1.f + __expf(-x));
}
__device__ __forceinline__ float tanh_fast(float x){
  return __fdividef(2.f, 1.f + __expf(-2.f * x)) - 1.f;
}

__device__ __forceinline__ void ldv16(const float* p, float v[16]){
  #pragma unroll
  for (int i = 0; i < 4; i++){
    float4 q = reinterpret_cast<const float4*>(p)[i];
    v[4*i+0] = q.x; v[4*i+1] = q.y; v[4*i+2] = q.z; v[4*i+3] = q.w;
  }
}

__device__ __forceinline__ float dot16(const float w[16], const float v[16]){
  float a0 = 0.f, a1 = 0.f, a2 = 0.f, a3 = 0.f;
  #pragma unroll
  for (int j = 0; j < 4; j++){
    a0 = fmaf(w[4*j+0], v[4*j+0], a0);
    a1 = fmaf(w[4*j+1], v[4*j+1], a1);
    a2 = fmaf(w[4*j+2], v[4*j+2], a2);
    a3 = fmaf(w[4*j+3], v[4*j+3], a3);
  }
  return (a0 + a1) + (a2 + a3);
}

// ============================================================================
// Phase 1: backward LSTM scan. One warp per batch element. x prefetched.
// ============================================================================
__global__ __launch_bounds__(64)
void lstm_bwd_kernel(const float* __restrict__ x,
                     const float* __restrict__ Wih,
                     const float* __restrict__ Whh,
                     const float* __restrict__ bih,
                     const float* __restrict__ bhh)
{
  const int l = threadIdx.x & 31;
  const int w = threadIdx.x >> 5;
  const int b = blockIdx.x * 2 + w;

  __shared__ __align__(16) float sH[2][16];
  float* hbuf = sH[w];

  const int r0 = l, r1 = l + 32;
  float w0[16], w1[16];
  #pragma unroll
  for (int j = 0; j < 16; j++){ w0[j] = Whh[r0*16 + j]; w1[j] = Whh[r1*16 + j]; }
  const float wx0 = Wih[r0], wx1 = Wih[r1];
  const float b0 = bih[r0] + bhh[r0];
  const float b1 = bih[r1] + bhh[r1];

  if (l < 16) hbuf[l] = 0.f;
  float c = 0.f;
  __syncwarp();

  const float* xb = x + b;
  float* hout = g_hseq + (size_t)b * 16;

  float xt = __ldg(xb + (size_t)(TL-1) * NB);   // prefetch first

  for (int t = TL - 1; t >= 0; --t){
    float xn = 0.f;
    if (t > 0) xn = __ldg(xb + (size_t)(t-1) * NB);   // prefetch next (off-chain)

    float hv[16]; ldv16(hbuf, hv);

    float a0 = fmaf(xt, wx0, b0);
    float a1 = fmaf(xt, wx1, b1);
    a0 += dot16(w0, hv);
    a1 += dot16(w1, hv);

    float p, q = 0.f;
    if (l < 16) { p = sigf(a0) * tanh_fast(a1); }     // sig(i)*tanh(g)
    else        { p = sigf(a0); q = sigf(a1); }       // sig(f), sig(o)
    float pf = __shfl_xor_sync(FULL, p, 16);
    float qo = __shfl_xor_sync(FULL, q, 16);
    __syncwarp();                                     // hbuf reads done
    if (l < 16){
      c = fmaf(pf, c, p);
      float hn = qo * tanh_fast(c);
      hbuf[l] = hn;
      hout[(size_t)t * (NB * 16) + l] = hn;
    }
    __syncwarp();
    xt = xn;
  }
}

// ============================================================================
// Phase 2: DKF recurrence ONLY (layers A, fused B+C, D). One warp per batch.
// dec/tr hoisted to kernel 3. h & eps double-buffered in registers.
// Fold: e1 = tanh(M @ a1 + bM), M = enc_W1 @ comb_W2, bM = enc_W1@cb2 + eb1.
// ============================================================================
__global__ __launch_bounds__(64)
void dkf_rec_kernel(const float* __restrict__ eps,
                    const float* __restrict__ cW1, const float* __restrict__ cb1,
                    const float* __restrict__ cW2, const float* __restrict__ cb2,
                    const float* __restrict__ eW1, const float* __restrict__ eb1,
                    const float* __restrict__ eW2, const float* __restrict__ eb2,
                    float* __restrict__ out)
{
  const int l = threadIdx.x & 31;
  const int w = threadIdx.x >> 5;
  const int b = blockIdx.x * 2 + w;
  const int lo = l & 15, half = l >> 4;

  __shared__ __align__(16) float sm[2][48];
  float* SA = &sm[w][0];    // a1 (16)
  float* SC = &sm[w][16];   // e1 (16)
  float* SZ = &sm[w][32];   // z  (16)

  // comb1 (16x32): lane pair (lo, lo+16): half0 = h-cols, half1 = z-cols
  float wA[16];
  #pragma unroll
  for (int j = 0; j < 16; j++) wA[j] = cW1[lo*32 + half*16 + j];
  const float bA = cb1[lo];

  // fused M row lo: M[lo][c] = sum_k eW1[lo*8+k] * cW2[k*16+c]
  float e1w[8];
  #pragma unroll
  for (int k = 0; k < 8; k++) e1w[k] = eW1[lo*8 + k];
  float wM[16];
  #pragma unroll
  for (int c = 0; c < 16; c++){
    float acc = 0.f;
    #pragma unroll
    for (int k = 0; k < 8; k++) acc = fmaf(e1w[k], cW2[k*16 + c], acc);
    wM[c] = acc;
  }
  float bM = eb1[lo];
  #pragma unroll
  for (int k = 0; k < 8; k++) bM = fmaf(e1w[k], cb2[k], bM);

  // enc2 (32x16): lane l owns row l
  float wD[16];
  #pragma unroll
  for (int j = 0; j < 16; j++) wD[j] = eW2[l*16 + j];
  const float bD = eb2[l];

  if (l < 16) SZ[lo] = 0.f;      // z0
  __syncwarp();

  const float* hbase = g_hseq + (size_t)b * 16;
  const float* ebase = eps + (size_t)b * 16;
  float*       zbase = g_zseq + (size_t)b * 16;
  float*       obase = out + (size_t)b * 66;

  float hv[16]; ldv16(hbase, hv);                 // h[0]
  float epsv = (l < 16) ? __ldg(ebase + lo) : 0.f;

  for (int t = 0; t < TL; ++t){
    // ---- prefetch next step (off the critical chain) ----
    float hn[16]; float epsn = 0.f;
    if (t + 1 < TL){
      ldv16(hbase + (size_t)(t+1) * (NB*16), hn);
      if (l < 16) epsn = __ldg(ebase + (size_t)(t+1) * (NB*16) + lo);
    } else {
      #pragma unroll
      for (int j = 0; j < 16; j++) hn[j] = 0.f;
    }
    float* outp = obase + (size_t)t * (NB * 66);

    // ---- Layer A: a1 = tanh(comb_W1 @ [h; z_prev] + b1) ----
    float in16[16];
    if (half){ ldv16(SZ, in16); }
    else {
      #pragma unroll
      for (int j = 0; j < 16; j++) in16[j] = hv[j];
    }
    float accA = dot16(wA, in16) + (half ? 0.f : bA);
    accA += __shfl_xor_sync(FULL, accA, 16);
    float a1 = tanh_fast(accA);
    if (l < 16) SA[lo] = a1;
    __syncwarp();

    // ---- Fused B+C: e1 = tanh(M @ a1 + bM) ----
    float av[16]; ldv16(SA, av);
    float e1 = tanh_fast(bM + dot16(wM, av));
    if (l < 16) SC[lo] = e1;
    __syncwarp();

    // ---- Layer D: e2 = enc_W2 @ e1 + eb2 ; sample z ----
    float ev[16]; ldv16(SC, ev);
    float e2 = bD + dot16(wD, ev);
    outp[2 + l] = e2;                   // mu_z / logvar_z
    float lvz = __shfl_xor_sync(FULL, e2, 16);
    float znew = fmaf(epsv, __expf(0.5f * lvz), e2);
    // safe: all SZ reads (layer A) are before the two syncwarps above
    if (l < 16){
      SZ[lo] = znew;
      zbase[(size_t)t * (NB*16) + lo] = znew;
    }
    __syncwarp();

    #pragma unroll
    for (int j = 0; j < 16; j++) hv[j] = hn[j];
    epsv = epsn;
  }
}

// ============================================================================
// Phase 3: decoder + transition. Fully parallel over all (t,b) positions.
// One thread per position; weights broadcast from shared memory.
// ============================================================================
#define OD_W1 0
#define OD_B1 256
#define OD_W2 272
#define OD_B2 304
#define OT_W1 308
#define OT_B1 564
#define OT_W2 580
#define OT_B2 1092
#define SW_TOT 1124

__device__ __forceinline__ float sdot16(const float* srow, const float v[16]){
  float a0 = 0.f, a1 = 0.f, a2 = 0.f, a3 = 0.f;
  #pragma unroll
  for (int j = 0; j < 4; j++){
    float4 q = reinterpret_cast<const float4*>(srow)[j];
    a0 = fmaf(q.x, v[4*j+0], a0);
    a1 = fmaf(q.y, v[4*j+1], a1);
    a2 = fmaf(q.z, v[4*j+2], a2);
    a3 = fmaf(q.w, v[4*j+3], a3);
  }
  return (a0 + a1) + (a2 + a3);
}

__global__ __launch_bounds__(256)
void dectr_kernel(const float* __restrict__ dW1, const float* __restrict__ db1,
                  const float* __restrict__ dW2, const float* __restrict__ db2,
                  const float* __restrict__ tW1, const float* __restrict__ tb1,
                  const float* __restrict__ tW2, const float* __restrict__ tb2,
                  float* __restrict__ out)
{
  __shared__ __align__(16) float s[SW_TOT];
  const int tid = threadIdx.x;
  for (int i = tid; i < 256; i += 256) s[OD_W1 + i] = dW1[i];
  if (tid < 16)  s[OD_B1 + tid] = db1[tid];
  if (tid < 32)  s[OD_W2 + tid] = dW2[tid];
  if (tid < 2)   s[OD_B2 + tid] = db2[tid];
  for (int i = tid; i < 256; i += 256) s[OT_W1 + i] = tW1[i];
  if (tid < 16)  s[OT_B1 + tid] = tb1[tid];
  for (int i = tid; i < 512; i += 256) s[OT_W2 + i] = tW2[i];
  if (tid < 32)  s[OT_B2 + tid] = tb2[tid];
  __syncthreads();

  const size_t pos = (size_t)blockIdx.x * 256 + tid;   // t*NB + b
  const float* zp_ptr = g_zseq + pos * 16;

  float z[16]; ldv16(zp_ptr, z);
  float zp[16];
  if (pos >= NB){ ldv16(zp_ptr - (size_t)NB * 16, zp); }
  else {
    #pragma unroll
    for (int j = 0; j < 16; j++) zp[j] = 0.f;
  }

  float* ob = out + pos * 66;

  // decoder: d1 = tanh(dW1 @ z + db1); d = dW2 @ d1 + db2
  float d1[16];
  #pragma unroll
  for (int r = 0; r < 16; r++)
    d1[r] = tanh_fast(s[OD_B1 + r] + sdot16(&s[OD_W1 + r*16], z));
  float2 dx;
  dx.x = s[OD_B2 + 0] + sdot16(&s[OD_W2 + 0],  d1);
  dx.y = s[OD_B2 + 1] + sdot16(&s[OD_W2 + 16], d1);
  *reinterpret_cast<float2*>(ob) = dx;    // mu_x, logvar_x

  // transition: t1 = tanh(tW1 @ z_prev + tb1); tr = tW2 @ t1 + tb2
  float t1[16];
  #pragma unroll
  for (int r = 0; r < 16; r++)
    t1[r] = tanh_fast(s[OT_B1 + r] + sdot16(&s[OT_W1 + r*16], zp));
  #pragma unroll
  for (int r = 0; r < 32; r += 2){
    float2 tv;
    tv.x = s[OT_B2 + r]     + sdot16(&s[OT_W2 + r*16],       t1);
    tv.y = s[OT_B2 + r + 1] + sdot16(&s[OT_W2 + (r+1)*16],   t1);
    *reinterpret_cast<float2*>(ob + 34 + r) = tv;   // mu_tr / logvar_tr
  }
}

extern "C" void kernel_launch(void* const* d_in, const int* in_sizes, int n_in,
                              void* d_out, int out_size)
{
  const float* x   = (const float*)d_in[0];
  const float* eps = (const float*)d_in[1];
  const float* Wih = (const float*)d_in[2];
  const float* Whh = (const float*)d_in[3];
  const float* bih = (const float*)d_in[4];
  const float* bhh = (const float*)d_in[5];
  const float* cW1 = (const float*)d_in[6];
  const float* cb1 = (const float*)d_in[7];
  const float* cW2 = (const float*)d_in[8];
  const float* cb2 = (const float*)d_in[9];
  const float* eW1 = (const float*)d_in[10];
  const float* eb1 = (const float*)d_in[11];
  const float* eW2 = (const float*)d_in[12];
  const float* eb2 = (const float*)d_in[13];
  const float* dW1 = (const float*)d_in[14];
  const float* db1 = (const float*)d_in[15];
  const float* dW2 = (const float*)d_in[16];
  const float* db2 = (const float*)d_in[17];
  const float* tW1 = (const float*)d_in[18];
  const float* tb1 = (const float*)d_in[19];
  const float* tW2 = (const float*)d_in[20];
  const float* tb2 = (const float*)d_in[21];
  float* out = (float*)d_out;

  lstm_bwd_kernel<<<NB/2, 64>>>(x, Wih, Whh, bih, bhh);
  dkf_rec_kernel<<<NB/2, 64>>>(eps, cW1, cb1, cW2, cb2, eW1, eb1, eW2, eb2, out);
  dectr_kernel<<<(TL*NB)/256, 256>>>(dW1, db1, dW2, db2, tW1, tb1, tW2, tb2, out);
}

// round 3
// speedup vs baseline: 1.1496x; 1.1496x over previous
#include <cuda_runtime.h>
#include <cstdint>
#include <cstddef>

#define TL 512
#define NB 2048
#define NB16 (NB*16)
#define FULL 0xffffffffu

// scratch: hproj_seq and z_seq, each T*B*16 floats = 64 MiB
__device__ float g_hproj[(size_t)TL * NB * 16];
__device__ float g_zseq[(size_t)TL * NB * 16];

__device__ __forceinline__ float sigf(float x){
  return __fdividef(1.f, 1.f + __expf(-x));
}
__device__ __forceinline__ float tanh_fast(float x){
  return __fdividef(2.f, 1.f + __expf(-2.f * x)) - 1.f;
}

__device__ __forceinline__ void ldv16(const float* p, float v[16]){
  #pragma unroll
  for (int i = 0; i < 4; i++){
    float4 q = reinterpret_cast<const float4*>(p)[i];
    v[4*i+0] = q.x; v[4*i+1] = q.y; v[4*i+2] = q.z; v[4*i+3] = q.w;
  }
}

__device__ __forceinline__ float dot16(const float w[16], const float v[16]){
  float a0 = 0.f, a1 = 0.f, a2 = 0.f, a3 = 0.f;
  #pragma unroll
  for (int j = 0; j < 4; j++){
    a0 = fmaf(w[4*j+0], v[4*j+0], a0);
    a1 = fmaf(w[4*j+1], v[4*j+1], a1);
    a2 = fmaf(w[4*j+2], v[4*j+2], a2);
    a3 = fmaf(w[4*j+3], v[4*j+3], a3);
  }
  return (a0 + a1) + (a2 + a3);
}

// ============================================================================
// Phase 1: backward LSTM scan, fused with hproj = cW1_h @ h + cb1.
// One warp per batch element. Writes g_hproj (NOT raw h).
// ============================================================================
__global__ __launch_bounds__(64)
void lstm_bwd_kernel(const float* __restrict__ x,
                     const float* __restrict__ Wih,
                     const float* __restrict__ Whh,
                     const float* __restrict__ bih,
                     const float* __restrict__ bhh,
                     const float* __restrict__ cW1,
                     const float* __restrict__ cb1)
{
  const int l = threadIdx.x & 31;
  const int w = threadIdx.x >> 5;
  const int b = blockIdx.x * 2 + w;
  const int lo = l & 15;

  __shared__ __align__(16) float sH[2][16];
  float* hbuf = sH[w];

  const int r0 = l, r1 = l + 32;
  float w0[16], w1[16];
  #pragma unroll
  for (int j = 0; j < 16; j++){ w0[j] = Whh[r0*16 + j]; w1[j] = Whh[r1*16 + j]; }
  const float wx0 = Wih[r0], wx1 = Wih[r1];
  const float b0 = bih[r0] + bhh[r0];
  const float b1 = bih[r1] + bhh[r1];

  // hproj row lo (h-columns 0..15 of comb_W1)
  float wHp[16];
  #pragma unroll
  for (int j = 0; j < 16; j++) wHp[j] = cW1[lo*32 + j];
  const float bHp = cb1[lo];

  if (l < 16) hbuf[l] = 0.f;
  float c = 0.f;
  __syncwarp();

  const float* xb = x + b;
  float* hpout = g_hproj + (size_t)b * 16 + lo;

  float xt = __ldg(xb + (size_t)(TL-1) * NB);   // prefetch first

  for (int t = TL - 1; t >= 0; --t){
    float xn = 0.f;
    if (t > 0) xn = __ldg(xb + (size_t)(t-1) * NB);   // prefetch next (off-chain)

    float hv[16]; ldv16(hbuf, hv);

    // hproj for h[t+1] (currently in hv); skip first iteration (h init)
    float hp = bHp + dot16(wHp, hv);
    if (l < 16 && t != TL - 1)
      hpout[(size_t)(t+1) * NB16] = hp;

    float a0 = fmaf(xt, wx0, b0);
    float a1 = fmaf(xt, wx1, b1);
    a0 += dot16(w0, hv);
    a1 += dot16(w1, hv);

    float p, q = 0.f;
    if (l < 16) { p = sigf(a0) * tanh_fast(a1); }     // sig(i)*tanh(g)
    else        { p = sigf(a0); q = sigf(a1); }       // sig(f), sig(o)
    float pf = __shfl_xor_sync(FULL, p, 16);
    float qo = __shfl_xor_sync(FULL, q, 16);
    __syncwarp();                                     // hbuf reads done
    if (l < 16){
      c = fmaf(pf, c, p);
      float hn = qo * tanh_fast(c);
      hbuf[l] = hn;
    }
    __syncwarp();
    xt = xn;
  }

  // epilogue: hproj[0] from final h (in hbuf)
  {
    float hv[16]; ldv16(hbuf, hv);
    float hp = bHp + dot16(wHp, hv);
    if (l < 16) hpout[0] = hp;
  }
}

// ============================================================================
// Phase 2: DKF recurrence. One warp per batch. Full-row lane ownership:
// lane r (= l&15) owns row r of layer A (z-half; h-half precomputed as hproj)
// and of fused layer M; lane l owns row l of enc_W2 (32 rows).
// Chain: LDS z -> dot -> tanh -> STS -> sync  (x2) -> D -> sample z.
// ============================================================================
__global__ __launch_bounds__(64)
void dkf_rec_kernel(const float* __restrict__ eps,
                    const float* __restrict__ cW1,
                    const float* __restrict__ cW2, const float* __restrict__ cb2,
                    const float* __restrict__ eW1, const float* __restrict__ eb1,
                    const float* __restrict__ eW2, const float* __restrict__ eb2,
                    float* __restrict__ out)
{
  const int l = threadIdx.x & 31;
  const int w = threadIdx.x >> 5;
  const int b = blockIdx.x * 2 + w;
  const int lo = l & 15;

  __shared__ __align__(16) float sm[2][48];
  float* SA = &sm[w][0];    // a1 (16)
  float* SC = &sm[w][16];   // e1 (16)
  float* SZ = &sm[w][32];   // z  (16)

  // layer A, z-columns of comb_W1, row lo (all lanes duplicate across halves)
  float wAz[16];
  #pragma unroll
  for (int j = 0; j < 16; j++) wAz[j] = cW1[lo*32 + 16 + j];

  // fused M row lo: M[lo][c] = sum_k eW1[lo*8+k] * cW2[k*16+c]
  float wM[16];
  float bM = eb1[lo];
  {
    float e1w[8];
    #pragma unroll
    for (int k = 0; k < 8; k++) e1w[k] = eW1[lo*8 + k];
    #pragma unroll
    for (int c = 0; c < 16; c++){
      float acc = 0.f;
      #pragma unroll
      for (int k = 0; k < 8; k++) acc = fmaf(e1w[k], cW2[k*16 + c], acc);
      wM[c] = acc;
    }
    #pragma unroll
    for (int k = 0; k < 8; k++) bM = fmaf(e1w[k], cb2[k], bM);
  }

  // enc2 (32x16): lane l owns row l
  float wD[16];
  #pragma unroll
  for (int j = 0; j < 16; j++) wD[j] = eW2[l*16 + j];
  const float bD = eb2[l];

  if (l < 16) SZ[lo] = 0.f;      // z0
  __syncwarp();

  const float* hpp = g_hproj + (size_t)b * 16 + lo;
  const float* epp = eps     + (size_t)b * 16 + lo;
  float*       zsp = g_zseq  + (size_t)b * 16 + lo;
  float*       outp = out    + (size_t)b * 66;

  float hpv  = __ldg(hpp);
  float epsv = __ldg(epp);

  for (int t = 0; t < TL; ++t){
    // prefetch next step's scalars (off-chain)
    float hpn = 0.f, epsn = 0.f;
    if (t + 1 < TL){
      hpn  = __ldg(hpp + (size_t)(t+1) * NB16);
      epsn = __ldg(epp + (size_t)(t+1) * NB16);
    }

    // ---- Layer A: a1[lo] = tanh(hproj[lo] + cW1_z[lo,:] @ z_prev) ----
    float zv[16]; ldv16(SZ, zv);
    float a1 = tanh_fast(hpv + dot16(wAz, zv));
    if (l < 16) SA[lo] = a1;
    __syncwarp();

    // ---- Fused B+C: e1[lo] = tanh(M[lo,:] @ a1 + bM) ----
    float av[16]; ldv16(SA, av);
    float e1 = tanh_fast(bM + dot16(wM, av));
    if (l < 16) SC[lo] = e1;
    __syncwarp();

    // ---- Layer D: e2[l] = eW2[l,:] @ e1 + bD ; sample z ----
    float ev[16]; ldv16(SC, ev);
    float e2 = bD + dot16(wD, ev);
    outp[2 + l] = e2;                           // mu_z / logvar_z (off-chain)
    float lvz = __shfl_xor_sync(FULL, e2, 16);  // lanes<16 get logvar
    float znew = fmaf(epsv, __expf(0.5f * lvz), e2);
    if (l < 16){
      SZ[lo] = znew;
      zsp[(size_t)t * NB16] = znew;
    }
    __syncwarp();

    hpv = hpn; epsv = epsn;
    outp += (size_t)NB * 66;
  }
}

// ============================================================================
// Phase 3: decoder + transition. Fully parallel over all (t,b) positions.
// ============================================================================
#define OD_W1 0
#define OD_B1 256
#define OD_W2 272
#define OD_B2 304
#define OT_W1 308
#define OT_B1 564
#define OT_W2 580
#define OT_B2 1092
#define SW_TOT 1124

__device__ __forceinline__ float sdot16(const float* srow, const float v[16]){
  float a0 = 0.f, a1 = 0.f, a2 = 0.f, a3 = 0.f;
  #pragma unroll
  for (int j = 0; j < 4; j++){
    float4 q = reinterpret_cast<const float4*>(srow)[j];
    a0 = fmaf(q.x, v[4*j+0], a0);
    a1 = fmaf(q.y, v[4*j+1], a1);
    a2 = fmaf(q.z, v[4*j+2], a2);
    a3 = fmaf(q.w, v[4*j+3], a3);
  }
  return (a0 + a1) + (a2 + a3);
}

__global__ __launch_bounds__(256)
void dectr_kernel(const float* __restrict__ dW1, const float* __restrict__ db1,
                  const float* __restrict__ dW2, const float* __restrict__ db2,
                  const float* __restrict__ tW1, const float* __restrict__ tb1,
                  const float* __restrict__ tW2, const float* __restrict__ tb2,
                  float* __restrict__ out)
{
  __shared__ __align__(16) float s[SW_TOT];
  const int tid = threadIdx.x;
  for (int i = tid; i < 256; i += 256) s[OD_W1 + i] = dW1[i];
  if (tid < 16)  s[OD_B1 + tid] = db1[tid];
  if (tid < 32)  s[OD_W2 + tid] = dW2[tid];
  if (tid < 2)   s[OD_B2 + tid] = db2[tid];
  for (int i = tid; i < 256; i += 256) s[OT_W1 + i] = tW1[i];
  if (tid < 16)  s[OT_B1 + tid] = tb1[tid];
  for (int i = tid; i < 512; i += 256) s[OT_W2 + i] = tW2[i];
  if (tid < 32)  s[OT_B2 + tid] = tb2[tid];
  __syncthreads();

  const size_t pos = (size_t)blockIdx.x * 256 + tid;   // t*NB + b
  const float* zp_ptr = g_zseq + pos * 16;

  float z[16]; ldv16(zp_ptr, z);
  float zp[16];
  if (pos >= NB){ ldv16(zp_ptr - (size_t)NB * 16, zp); }
  else {
    #pragma unroll
    for (int j = 0; j < 16; j++) zp[j] = 0.f;
  }

  float* ob = out + pos * 66;

  // decoder: d1 = tanh(dW1 @ z + db1); d = dW2 @ d1 + db2
  float d1[16];
  #pragma unroll
  for (int r = 0; r < 16; r++)
    d1[r] = tanh_fast(s[OD_B1 + r] + sdot16(&s[OD_W1 + r*16], z));
  float2 dx;
  dx.x = s[OD_B2 + 0] + sdot16(&s[OD_W2 + 0],  d1);
  dx.y = s[OD_B2 + 1] + sdot16(&s[OD_W2 + 16], d1);
  *reinterpret_cast<float2*>(ob) = dx;    // mu_x, logvar_x

  // transition: t1 = tanh(tW1 @ z_prev + tb1); tr = tW2 @ t1 + tb2
  float t1[16];
  #pragma unroll
  for (int r = 0; r < 16; r++)
    t1[r] = tanh_fast(s[OT_B1 + r] + sdot16(&s[OT_W1 + r*16], zp));
  #pragma unroll
  for (int r = 0; r < 32; r += 2){
    float2 tv;
    tv.x = s[OT_B2 + r]     + sdot16(&s[OT_W2 + r*16],       t1);
    tv.y = s[OT_B2 + r + 1] + sdot16(&s[OT_W2 + (r+1)*16],   t1);
    *reinterpret_cast<float2*>(ob + 34 + r) = tv;   // mu_tr / logvar_tr
  }
}

extern "C" void kernel_launch(void* const* d_in, const int* in_sizes, int n_in,
                              void* d_out, int out_size)
{
  const float* x   = (const float*)d_in[0];
  const float* eps = (const float*)d_in[1];
  const float* Wih = (const float*)d_in[2];
  const float* Whh = (const float*)d_in[3];
  const float* bih = (const float*)d_in[4];
  const float* bhh = (const float*)d_in[5];
  const float* cW1 = (const float*)d_in[6];
  const float* cb1 = (const float*)d_in[7];
  const float* cW2 = (const float*)d_in[8];
  const float* cb2 = (const float*)d_in[9];
  const float* eW1 = (const float*)d_in[10];
  const float* eb1 = (const float*)d_in[11];
  const float* eW2 = (const float*)d_in[12];
  const float* eb2 = (const float*)d_in[13];
  const float* dW1 = (const float*)d_in[14];
  const float* db1 = (const float*)d_in[15];
  const float* dW2 = (const float*)d_in[16];
  const float* db2 = (const float*)d_in[17];
  const float* tW1 = (const float*)d_in[18];
  const float* tb1 = (const float*)d_in[19];
  const float* tW2 = (const float*)d_in[20];
  const float* tb2 = (const float*)d_in[21];
  float* out = (float*)d_out;

  lstm_bwd_kernel<<<NB/2, 64>>>(x, Wih, Whh, bih, bhh, cW1, cb1);
  dkf_rec_kernel<<<NB/2, 64>>>(eps, cW1, cW2, cb2, eW1, eb1, eW2, eb2, out);
  dectr_kernel<<<(TL*NB)/256, 256>>>(dW1, db1, dW2, db2, tW1, tb1, tW2, tb2, out);
}